// round 7
// baseline (speedup 1.0000x reference)
#include <cuda_runtime.h>
#include <cstdint>

// out[b,h,i,j] = scores[b,h,i,j] + sum_d q[b,h,i,d] * E[(j-i)+4096, d]
// B=2,H=16,S=2048,D=64.
//
// Per 64x128 (i,j) tile (Toeplitz): G[i,r] = Q(64x64) . E_rows(192x64)^T,
// E_rows = 192 contiguous rel_emb rows; out j = r + i - 63.
// mma.sync.m16n8k8 tf32 (portable PTX; tcgen05 is gated off on the plain
// sm_103 target this harness emits).
// 8 warps = 4 m-tiles x 2 n-half-bands (9 of 18 band tiles each) => acc only
// 36 regs => __launch_bounds__(256,3) fits 3 CTAs/SM (24 warps) with 68KB
// SMEM/CTA. That's the fix for the R6 latency-bound profile (L1 62% unsat).
// Inputs rounded to tf32 via cvt.rna at stage time. Diagonal scatter to sG
// (aliases Q/E), then fully coalesced float4 (scores + sG) -> out.

#define S_LEN 2048
#define TI 64            // tile rows (i)
#define TJ 128           // tile cols (j)
#define ER 192           // E rows staged (needs 191)
#define QP 68            // pitches: bank = 4*gid+tig, bijective across warp
#define EP 68
#define GP 132
#define SMEM_U32 (TI * QP + ER * EP)       // 17408 words
#define SMEM_BYTES (SMEM_U32 * 4)          // 69632 (sG 64*132*4=33792 aliases)

__device__ __forceinline__ uint32_t f2tf32(float f) {
    uint32_t r;
    asm("cvt.rna.tf32.f32 %0, %1;" : "=r"(r) : "f"(f));
    return r;
}

__device__ __forceinline__ void mma_tf32(float* c,
                                         uint32_t a0, uint32_t a1,
                                         uint32_t a2, uint32_t a3,
                                         uint32_t b0, uint32_t b1) {
    asm volatile(
        "mma.sync.aligned.m16n8k8.row.col.f32.tf32.tf32.f32 "
        "{%0,%1,%2,%3}, {%4,%5,%6,%7}, {%8,%9}, {%0,%1,%2,%3};"
        : "+f"(c[0]), "+f"(c[1]), "+f"(c[2]), "+f"(c[3])
        : "r"(a0), "r"(a1), "r"(a2), "r"(a3), "r"(b0), "r"(b1));
}

__global__ __launch_bounds__(256, 3)
void relpos_mma(const float* __restrict__ query,
                const float* __restrict__ scores,
                const float* __restrict__ rel,
                float* __restrict__ out)
{
    extern __shared__ uint32_t smem[];
    uint32_t* Qs = smem;              // [64][QP] tf32 bits
    uint32_t* Es = smem + TI * QP;    // [192][EP] tf32 bits

    const int tid  = threadIdx.x;
    const int wid  = tid >> 5;
    const int lane = tid & 31;
    const int gid  = lane >> 2;       // 0..7
    const int tig  = lane & 3;        // 0..3
    const int bh = blockIdx.z;
    const int i0 = blockIdx.y * TI;
    const int j0 = blockIdx.x * TJ;

    // ---- Stage Q tile (64x64) to SMEM, rounding to tf32 (RN) ----
    const float* qg = query + ((size_t)bh * S_LEN + i0) * 64;
    #pragma unroll
    for (int k = 0; k < 4; ++k) {
        int idx = tid + k * 256;              // 1024 float4
        int row = idx >> 4;
        int c   = (idx & 15) << 2;
        float4 v = *(const float4*)(qg + row * 64 + c);
        uint32_t* d = Qs + row * QP + c;
        d[0] = f2tf32(v.x); d[1] = f2tf32(v.y);
        d[2] = f2tf32(v.z); d[3] = f2tf32(v.w);
    }
    // ---- Stage E tile: 192 contiguous rows from rBase (always in-bounds) ----
    // r = j - i + 63 in [0,190]; global row = rBase + r.
    const int rBase = 4096 - 63 + (j0 - i0);   // [2049, 5953]; +191 < 8192
    const float* eg = rel + (size_t)rBase * 64;
    #pragma unroll
    for (int k = 0; k < 12; ++k) {
        int idx = tid + k * 256;              // 3072 float4
        int row = idx >> 4;
        int c   = (idx & 15) << 2;
        float4 v = *(const float4*)(eg + row * 64 + c);
        uint32_t* d = Es + row * EP + c;
        d[0] = f2tf32(v.x); d[1] = f2tf32(v.y);
        d[2] = f2tf32(v.z); d[3] = f2tf32(v.w);
    }
    __syncthreads();

    // ---- Band mainloop ----
    // warp = (mi, nh): m-tile mi rows 16mi..16mi+15; band n-tiles
    // [6-2mi, 23-2mi] (18 tiles), this warp takes 9 starting at +9*nh.
    const int mi = wid & 3;
    const int nh = wid >> 2;
    const int nBase = 6 - 2 * mi + 9 * nh;

    float acc[9][4];
    #pragma unroll
    for (int t = 0; t < 9; ++t) {
        acc[t][0] = 0.f; acc[t][1] = 0.f; acc[t][2] = 0.f; acc[t][3] = 0.f;
    }

    const uint32_t* aP = Qs + (16 * mi + gid) * QP + tig;
    const uint32_t* bP = Es + (8 * nBase + gid) * EP + tig;

    #pragma unroll
    for (int k = 0; k < 8; ++k) {
        uint32_t a0 = aP[0];
        uint32_t a1 = aP[8 * QP];
        uint32_t a2 = aP[4];
        uint32_t a3 = aP[8 * QP + 4];
        #pragma unroll
        for (int t = 0; t < 9; ++t) {
            const uint32_t* bp = bP + t * (8 * EP);
            mma_tf32(acc[t], a0, a1, a2, a3, bp[0], bp[4]);
        }
        aP += 8;
        bP += 8;
    }

    __syncthreads();                 // all warps done reading Qs/Es
    float* sG = (float*)smem;        // alias: [64][GP], G[i][j]

    // ---- Scatter fragments diagonal-reindexed: j = r + i - 63 ----
    {
        const int iA = 16 * mi + gid;
        const int iB = iA + 8;
        #pragma unroll
        for (int t = 0; t < 9; ++t) {
            int r0 = 8 * (nBase + t) + 2 * tig;
            int jA = r0 + iA - 63;
            int jB = r0 + iB - 63;
            if ((unsigned)jA       < (unsigned)TJ) sG[iA * GP + jA]     = acc[t][0];
            if ((unsigned)(jA + 1) < (unsigned)TJ) sG[iA * GP + jA + 1] = acc[t][1];
            if ((unsigned)jB       < (unsigned)TJ) sG[iB * GP + jB]     = acc[t][2];
            if ((unsigned)(jB + 1) < (unsigned)TJ) sG[iB * GP + jB + 1] = acc[t][3];
        }
    }
    __syncthreads();

    // ---- Coalesced epilogue: out = scores + sG ----
    const size_t gbase = ((size_t)bh * S_LEN + i0) * S_LEN + j0;
    const int c4 = (tid & 31) << 2;
    #pragma unroll
    for (int k = 0; k < 8; ++k) {
        int il = (tid >> 5) + 8 * k;
        float4 s = *(const float4*)(scores + gbase + (size_t)il * S_LEN + c4);
        float4 g = *(const float4*)(sG + il * GP + c4);
        float4 o;
        o.x = s.x + g.x;
        o.y = s.y + g.y;
        o.z = s.z + g.z;
        o.w = s.w + g.w;
        *(float4*)(out + gbase + (size_t)il * S_LEN + c4) = o;
    }
}

extern "C" void kernel_launch(void* const* d_in, const int* in_sizes, int n_in,
                              void* d_out, int out_size) {
    const float* query  = nullptr;  // 2*16*2048*64   = 4194304
    const float* scores = nullptr;  // 2*16*2048*2048 = 134217728
    const float* rel    = nullptr;  // 8192*64        = 524288
    for (int i = 0; i < n_in; ++i) {
        if (in_sizes[i] == 4194304)        query  = (const float*)d_in[i];
        else if (in_sizes[i] == 134217728) scores = (const float*)d_in[i];
        else if (in_sizes[i] == 524288)    rel    = (const float*)d_in[i];
    }

    cudaFuncSetAttribute(relpos_mma,
                         cudaFuncAttributeMaxDynamicSharedMemorySize,
                         SMEM_BYTES);

    dim3 grid(S_LEN / TJ, S_LEN / TI, 32);  // (16, 32, B*H)
    relpos_mma<<<grid, 256, SMEM_BYTES>>>(query, scores, rel, (float*)d_out);
}

// round 8
// speedup vs baseline: 1.2936x; 1.2936x over previous
#include <cuda_runtime.h>
#include <cuda_fp16.h>
#include <cstdint>

// out[b,h,i,j] = scores[b,h,i,j] + sum_d q[b,h,i,d] * E[(j-i)+4096, d]
// B=2,H=16,S=2048,D=64.
//
// 64x128 (i,j) tile. G[i,r] = Q(64x64) . E_rows(192x64)^T, j = r + i - 63.
// fp16 mma.sync m16n8k16 (same 10-bit mantissa as tf32; k=16 halves LDS and
// tensor instr count). Scores tile arrives via cp.async.bulk (TMA engine) into
// SMEM overlapping the mainloop; scatter does sS[i][j] += G; result leaves via
// cp.async.bulk store. Global streams thus bypass the L1tex wavefront path,
// which R6/R7 profiling showed to be the binding ~2 wf/cyc/SM resource.
// 8 warps = 4 m-tiles x 2 n-half-bands (9 tiles each); 3 CTAs/SM (69KB SMEM).

#define S_LEN 2048
#define TI 64
#define TJ 128
#define ER 192
#define QPW 36           // Q pitch in u32 (=72 halfs): bank 4*gid+tig bijective
#define EPW 36
#define GP  132          // sS pitch (floats); rows 528B apart (16B aligned)

#define SMEM_Q_U32 (TI * QPW)            // 2304
#define SMEM_E_U32 (ER * EPW)            // 6912
#define SMEM_S_U32 (TI * GP)             // 8448
#define SMEM_BAR_U32 8
#define SMEM_U32 (SMEM_Q_U32 + SMEM_E_U32 + SMEM_S_U32 + SMEM_BAR_U32)
#define SMEM_BYTES (SMEM_U32 * 4)        // 70688

__device__ __forceinline__ uint32_t smem_u32p(const void* p) {
    uint32_t a;
    asm("{ .reg .u64 t; cvta.to.shared.u64 t, %1; cvt.u32.u64 %0, t; }"
        : "=r"(a) : "l"(p));
    return a;
}

#define MBARRIER_INIT(mbar, cnt) \
    asm volatile("mbarrier.init.shared.b64 [%0], %1;" \
                 :: "r"((uint32_t)(mbar)), "r"((uint32_t)(cnt)) : "memory")
#define MBARRIER_EXPECT_TX(mbar, bytes) \
    asm volatile("mbarrier.arrive.expect_tx.shared.b64 _, [%0], %1;" \
                 :: "r"((uint32_t)(mbar)), "r"((uint32_t)(bytes)) : "memory")
#define MBARRIER_WAIT_PARITY(mbar, par) do {                                   \
    asm volatile(                                                              \
        "{\n\t.reg .pred P1;\n\t"                                              \
        "WAIT_LOOP_%=:\n\t"                                                    \
        "mbarrier.try_wait.parity.acquire.cta.shared::cta.b64 P1, [%0], %1, 0x989680;\n\t" \
        "@P1 bra.uni WAIT_DONE_%=;\n\t"                                        \
        "bra.uni WAIT_LOOP_%=;\n\t"                                            \
        "WAIT_DONE_%=:\n\t}"                                                   \
        :: "r"((uint32_t)(mbar)), "r"((uint32_t)(par)) : "memory");            \
} while (0)
#define FENCE_PROXY_ASYNC() asm volatile("fence.proxy.async.shared::cta;" ::: "memory")

#define BULK_G2S(dst, src, bytes, mbar) \
    asm volatile("cp.async.bulk.shared::cluster.global.mbarrier::complete_tx::bytes " \
                 "[%0], [%1], %2, [%3];" \
                 :: "r"((uint32_t)(dst)), "l"(src), "r"((uint32_t)(bytes)), \
                    "r"((uint32_t)(mbar)) : "memory")
#define BULK_S2G(dst, src, bytes) \
    asm volatile("cp.async.bulk.global.shared::cta.bulk_group [%0], [%1], %2;" \
                 :: "l"(dst), "r"((uint32_t)(src)), "r"((uint32_t)(bytes)) : "memory")
#define BULK_COMMIT() asm volatile("cp.async.bulk.commit_group;" ::: "memory")
#define BULK_WAIT0()  asm volatile("cp.async.bulk.wait_group 0;" ::: "memory")

__device__ __forceinline__ void mma_f16(float* c,
                                        uint32_t a0, uint32_t a1,
                                        uint32_t a2, uint32_t a3,
                                        uint32_t b0, uint32_t b1) {
    asm volatile(
        "mma.sync.aligned.m16n8k16.row.col.f32.f16.f16.f32 "
        "{%0,%1,%2,%3}, {%4,%5,%6,%7}, {%8,%9}, {%0,%1,%2,%3};"
        : "+f"(c[0]), "+f"(c[1]), "+f"(c[2]), "+f"(c[3])
        : "r"(a0), "r"(a1), "r"(a2), "r"(a3), "r"(b0), "r"(b1));
}

__device__ __forceinline__ uint32_t pack_h2(float lo, float hi) {
    __half2 h = __floats2half2_rn(lo, hi);   // .x = lo
    return *(uint32_t*)&h;
}

__global__ __launch_bounds__(256, 3)
void relpos_mma(const float* __restrict__ query,
                const float* __restrict__ scores,
                const float* __restrict__ rel,
                float* __restrict__ out)
{
    extern __shared__ uint32_t smem[];
    uint32_t* Qs = smem;                       // [64][QPW] packed half2
    uint32_t* Es = smem + SMEM_Q_U32;          // [192][EPW]
    float*    sS = (float*)(smem + SMEM_Q_U32 + SMEM_E_U32);  // [64][GP]
    uint32_t* bar = smem + SMEM_Q_U32 + SMEM_E_U32 + SMEM_S_U32;
    const uint32_t barAddr = smem_u32p(bar);

    const int tid  = threadIdx.x;
    const int wid  = tid >> 5;
    const int lane = tid & 31;
    const int gid  = lane >> 2;
    const int tig  = lane & 3;
    const int bh = blockIdx.z;
    const int i0 = blockIdx.y * TI;
    const int j0 = blockIdx.x * TJ;
    const size_t gbase = ((size_t)bh * S_LEN + i0) * S_LEN + j0;

    // ---- Kick off async scores tile load (TMA engine), 64 rows x 512B ----
    if (tid == 0) {
        MBARRIER_INIT(barAddr, 1);
        FENCE_PROXY_ASYNC();
        MBARRIER_EXPECT_TX(barAddr, TI * TJ * 4);
        const uint32_t sSaddr = smem_u32p(sS);
        const float* srow = scores + gbase;
        #pragma unroll 4
        for (int il = 0; il < TI; ++il)
            BULK_G2S(sSaddr + il * (GP * 4), srow + (size_t)il * S_LEN, TJ * 4, barAddr);
    }

    // ---- Stage Q tile (64x64) as fp16 ----
    const float* qg = query + ((size_t)bh * S_LEN + i0) * 64;
    #pragma unroll
    for (int k = 0; k < 4; ++k) {
        int idx = tid + k * 256;               // 1024 float4
        int row = idx >> 4;
        int c2  = (idx & 15) << 1;             // u32 col (2 per float4)
        float4 v = *(const float4*)(qg + row * 64 + (c2 << 1));
        Qs[row * QPW + c2]     = pack_h2(v.x, v.y);
        Qs[row * QPW + c2 + 1] = pack_h2(v.z, v.w);
    }
    // ---- Stage E tile: 192 contiguous rows (r = j-i+63 in [0,190]) ----
    const int rBase = 4096 - 63 + (j0 - i0);   // [2049,5953]; +191 < 8192
    const float* eg = rel + (size_t)rBase * 64;
    #pragma unroll
    for (int k = 0; k < 12; ++k) {
        int idx = tid + k * 256;               // 3072 float4
        int row = idx >> 4;
        int c2  = (idx & 15) << 1;
        float4 v = *(const float4*)(eg + row * 64 + (c2 << 1));
        Es[row * EPW + c2]     = pack_h2(v.x, v.y);
        Es[row * EPW + c2 + 1] = pack_h2(v.z, v.w);
    }
    __syncthreads();

    // ---- Band mainloop: warp (mi, nh); n-tiles [6-2mi .. 23-2mi], 9 each ----
    const int mi = wid & 3;
    const int nh = wid >> 2;
    const int nBase = 6 - 2 * mi + 9 * nh;

    float acc[9][4];
    #pragma unroll
    for (int t = 0; t < 9; ++t) {
        acc[t][0] = 0.f; acc[t][1] = 0.f; acc[t][2] = 0.f; acc[t][3] = 0.f;
    }

    const uint32_t* aP = Qs + (16 * mi + gid) * QPW + tig;
    const uint32_t* bP = Es + (8 * nBase + gid) * EPW + tig;

    #pragma unroll
    for (int k = 0; k < 4; ++k) {              // K = 64, 16 per MMA
        uint32_t a0 = aP[0];
        uint32_t a1 = aP[8 * QPW];
        uint32_t a2 = aP[4];
        uint32_t a3 = aP[8 * QPW + 4];
        #pragma unroll
        for (int t = 0; t < 9; ++t) {
            const uint32_t* bp = bP + t * (8 * EPW);
            mma_f16(acc[t], a0, a1, a2, a3, bp[0], bp[4]);
        }
        aP += 8;                               // +16 halfs
        bP += 8;
    }

    // ---- Wait for scores tile, scatter-accumulate: sS[i][j] += G ----
    MBARRIER_WAIT_PARITY(barAddr, 0);
    {
        const int iA = 16 * mi + gid;
        const int iB = iA + 8;
        #pragma unroll
        for (int t = 0; t < 9; ++t) {
            int r0 = 8 * (nBase + t) + 2 * tig;
            int jA = r0 + iA - 63;
            int jB = r0 + iB - 63;
            if ((unsigned)jA       < (unsigned)TJ) sS[iA * GP + jA]     += acc[t][0];
            if ((unsigned)(jA + 1) < (unsigned)TJ) sS[iA * GP + jA + 1] += acc[t][1];
            if ((unsigned)jB       < (unsigned)TJ) sS[iB * GP + jB]     += acc[t][2];
            if ((unsigned)(jB + 1) < (unsigned)TJ) sS[iB * GP + jB + 1] += acc[t][3];
        }
    }
    FENCE_PROXY_ASYNC();
    __syncthreads();

    // ---- Bulk store result rows (threads 0..63, one row each) ----
    if (tid < TI) {
        const uint32_t sSaddr = smem_u32p(sS);
        BULK_S2G(out + gbase + (size_t)tid * S_LEN, sSaddr + tid * (GP * 4), TJ * 4);
        BULK_COMMIT();
        BULK_WAIT0();
    }
    __syncthreads();
}

extern "C" void kernel_launch(void* const* d_in, const int* in_sizes, int n_in,
                              void* d_out, int out_size) {
    const float* query  = nullptr;  // 2*16*2048*64   = 4194304
    const float* scores = nullptr;  // 2*16*2048*2048 = 134217728
    const float* rel    = nullptr;  // 8192*64        = 524288
    for (int i = 0; i < n_in; ++i) {
        if (in_sizes[i] == 4194304)        query  = (const float*)d_in[i];
        else if (in_sizes[i] == 134217728) scores = (const float*)d_in[i];
        else if (in_sizes[i] == 524288)    rel    = (const float*)d_in[i];
    }

    cudaFuncSetAttribute(relpos_mma,
                         cudaFuncAttributeMaxDynamicSharedMemorySize,
                         SMEM_BYTES);

    dim3 grid(S_LEN / TJ, S_LEN / TI, 32);  // (16, 32, B*H)
    relpos_mma<<<grid, 256, SMEM_BYTES>>>(query, scores, rel, (float*)d_out);
}